// round 1
// baseline (speedup 1.0000x reference)
#include <cuda_runtime.h>
#include <cuda_bf16.h>

#define NLAGS   250
#define LPAD    256          // padded lag count (lags >= 250 computed on zero-padded halo, discarded)
#define TILE_J  1024
#define NBLOCKS 592
#define THREADS 256
#define GPAD_SZ 1440         // phys size for logical 1280 floats with i + (i>>3) padding

// Deterministic two-stage reduction scratch (no allocs allowed)
__device__ float g_partial[NBLOCKS * LPAD];
__device__ float g_sums[NBLOCKS * 4];

// ---------------------------------------------------------------------------
// Kernel A: per-block partial cross-correlations for 256 lags + partial sums.
// Each warp handles 128 j's per tile; each lane handles 8 consecutive lags
// with a register sliding window over g (conflict-free via padded smem).
// ---------------------------------------------------------------------------
__global__ void __launch_bounds__(THREADS) cccorr_kernel(const float* __restrict__ p,
                                                         const float* __restrict__ g,
                                                         int T) {
    __shared__ float p_s[TILE_J];
    __shared__ float g_s[GPAD_SZ];
    __shared__ float red[8 * LPAD];

    const int tid    = threadIdx.x;
    const int lane   = tid & 31;
    const int warpId = tid >> 5;
    const int jj0    = warpId * 128;   // warp's j sub-slice within tile
    const int n0     = lane * 8;       // lane's base lag

    float acc[8];
#pragma unroll
    for (int k = 0; k < 8; k++) acc[k] = 0.f;
    float sp = 0.f, sp2 = 0.f, sg = 0.f, sg2 = 0.f;

    const int ntiles = (T + TILE_J - 1) / TILE_J;
    for (int tile = blockIdx.x; tile < ntiles; tile += NBLOCKS) {
        const int base = tile * TILE_J;

        // Load p tile (zero-padded) + accumulate sums
        for (int i = tid; i < TILE_J; i += THREADS) {
            int gi = base + i;
            float v = (gi < T) ? p[gi] : 0.f;
            p_s[i] = v;
            sp += v; sp2 += v * v;
        }
        // Load g tile + 256 halo into padded smem (zero-padded past T)
        for (int i = tid; i < TILE_J + LPAD; i += THREADS) {
            int gi = base + i;
            float v = (gi < T) ? g[gi] : 0.f;
            g_s[i + (i >> 3)] = v;
            if (i < TILE_J) { sg += v; sg2 += v * v; }
        }
        __syncthreads();

        // Sliding-window cross-correlation: acc[k] += sum_j p[j] * g[j + n0 + k]
        float w[8];
#pragma unroll
        for (int k = 0; k < 8; k++) {
            int li = jj0 + n0 + k;
            w[k] = g_s[li + (li >> 3)];
        }
#pragma unroll 8
        for (int jj = 0; jj < 128; jj++) {
            float pv = p_s[jj0 + jj];
#pragma unroll
            for (int k = 0; k < 8; k++) acc[k] = fmaf(pv, w[k], acc[k]);
            int li = jj0 + jj + n0 + 8;        // next window top (lane-stride 9 in phys -> no conflict)
            float nv = g_s[li + (li >> 3)];
#pragma unroll
            for (int k = 0; k < 7; k++) w[k] = w[k + 1];
            w[7] = nv;
        }
        __syncthreads();
    }

    // Reduce 8 warps' partials per lag -> one partial row per block
#pragma unroll
    for (int k = 0; k < 8; k++) red[warpId * LPAD + n0 + k] = acc[k];
    __syncthreads();
    {
        float s = 0.f;
#pragma unroll
        for (int w = 0; w < 8; w++) s += red[w * LPAD + tid];
        g_partial[blockIdx.x * LPAD + tid] = s;
    }

    // Reduce the 4 scalar sums
#pragma unroll
    for (int off = 16; off; off >>= 1) {
        sp  += __shfl_down_sync(0xFFFFFFFFu, sp,  off);
        sp2 += __shfl_down_sync(0xFFFFFFFFu, sp2, off);
        sg  += __shfl_down_sync(0xFFFFFFFFu, sg,  off);
        sg2 += __shfl_down_sync(0xFFFFFFFFu, sg2, off);
    }
    __shared__ float sred[8][4];
    if (lane == 0) {
        sred[warpId][0] = sp;  sred[warpId][1] = sp2;
        sred[warpId][2] = sg;  sred[warpId][3] = sg2;
    }
    __syncthreads();
    if (tid < 4) {
        float t = 0.f;
#pragma unroll
        for (int w = 0; w < 8; w++) t += sred[w][tid];
        g_sums[blockIdx.x * 4 + tid] = t;
    }
}

// ---------------------------------------------------------------------------
// Kernel B: deterministic finalize. Reduce block partials, compute tail sums,
// the 250 CCCs, and the output scalar.
// ---------------------------------------------------------------------------
__global__ void __launch_bounds__(THREADS) finalize_kernel(const float* __restrict__ p,
                                                           int T,
                                                           float* __restrict__ out) {
    __shared__ float tot[4];
    __shared__ float ptail[LPAD];    // ptail[k] = p[T-k] for k>=1
    __shared__ float ptail2[LPAD];
    __shared__ float sredc[LPAD];
    __shared__ float cccs[LPAD];

    const int tid = threadIdx.x;

    // Cross-correlation for lag = tid (coalesced over blocks)
    float cross = 0.f;
    for (int b = 0; b < NBLOCKS; b++) cross += g_partial[b * LPAD + tid];

    // Global sums: column (tid&3) over blocks, strided
    {
        float s = 0.f;
        for (int b = (tid >> 2); b < NBLOCKS; b += 64) s += g_sums[b * 4 + (tid & 3)];
        sredc[tid] = s;
    }
    __syncthreads();
    if (tid < 4) {
        float t = 0.f;
        for (int i = 0; i < 64; i++) t += sredc[tid + 4 * i];
        tot[tid] = t;
    }
    // Tail values of p
    if (tid >= 1) {
        float v = p[T - tid];
        ptail[tid] = v;
        ptail2[tid] = v * v;
    } else {
        ptail[0] = 0.f; ptail2[0] = 0.f;
    }
    __syncthreads();

    const float Sp  = tot[0], Sp2 = tot[1];
    const float Sg  = tot[2], Sg2 = tot[3];
    const float Tf  = (float)T;
    const float mean_gt = Sg / Tf;
    const float var_gt  = (Sg2 - Tf * mean_gt * mean_gt) / (Tf - 1.f);

    float ccc = 0.f;
    if (tid < NLAGS) {
        float tp = 0.f, tp2 = 0.f;
        for (int k = 1; k <= tid; k++) { tp += ptail[k]; tp2 += ptail2[k]; }
        float Spn  = Sp  - tp;     // sum of p[0 : T-n]
        float Spn2 = Sp2 - tp2;
        float mean_pred = Spn / Tf;
        float var_pred  = (Spn2 - Tf * mean_pred * mean_pred) / (Tf - 1.f);
        float cov = (cross - mean_gt * Spn) / Tf;   // population covariance
        float dm  = mean_gt - mean_pred;
        float denom = var_gt + var_pred + dm * dm;
        ccc = 2.f * cov / denom;
    }
    cccs[tid] = ccc;
    __syncthreads();
#pragma unroll
    for (int off = 128; off; off >>= 1) {
        if (tid < off) cccs[tid] += cccs[tid + off];
        __syncthreads();
    }
    if (tid == 0) out[0] = 1.f - cccs[0] / (float)NLAGS;
}

extern "C" void kernel_launch(void* const* d_in, const int* in_sizes, int n_in,
                              void* d_out, int out_size) {
    const float* pred = (const float*)d_in[0];
    const float* gt   = (const float*)d_in[1];
    float* out = (float*)d_out;
    int T = in_sizes[0];

    cccorr_kernel<<<NBLOCKS, THREADS>>>(pred, gt, T);
    finalize_kernel<<<1, THREADS>>>(pred, T, out);
}

// round 3
// speedup vs baseline: 1.0513x; 1.0513x over previous
#include <cuda_runtime.h>
#include <cuda_bf16.h>

#define NLAGS   250
#define LPAD    256          // padded lag count (lags >= 250 computed on zero-padded halo, discarded)
#define TILE_J  1024
#define NBLOCKS 592          // 4 CTAs/SM * 148 SMs
#define THREADS 256
#define GPAD_SZ 1440         // phys size for logical 1280 floats with i + (i>>3) padding

// Deterministic two-stage reduction scratch (no allocs allowed)
__device__ float g_partial[NBLOCKS * LPAD];
__device__ float4 g_sums4[NBLOCKS];

// ---------------------------------------------------------------------------
// Kernel A: per-block partial cross-correlations for 256 lags + partial sums.
// Each warp handles 128 j's per tile; each lane handles 8 consecutive lags
// with a register sliding window over g (conflict-free via padded smem).
// ---------------------------------------------------------------------------
__global__ void __launch_bounds__(THREADS) cccorr_kernel(const float* __restrict__ p,
                                                         const float* __restrict__ g,
                                                         int T) {
    __shared__ float p_s[TILE_J];
    __shared__ float g_s[GPAD_SZ];
    __shared__ float red[8 * LPAD];

    const int tid    = threadIdx.x;
    const int lane   = tid & 31;
    const int warpId = tid >> 5;
    const int jj0    = warpId * 128;   // warp's j sub-slice within tile
    const int n0     = lane * 8;       // lane's base lag

    float acc[8];
#pragma unroll
    for (int k = 0; k < 8; k++) acc[k] = 0.f;
    float sp = 0.f, sp2 = 0.f, sg = 0.f, sg2 = 0.f;

    const int ntiles = (T + TILE_J - 1) / TILE_J;
    for (int tile = blockIdx.x; tile < ntiles; tile += NBLOCKS) {
        const int base = tile * TILE_J;

        // Load p tile (zero-padded) + accumulate sums
        for (int i = tid; i < TILE_J; i += THREADS) {
            int gi = base + i;
            float v = (gi < T) ? p[gi] : 0.f;
            p_s[i] = v;
            sp += v; sp2 += v * v;
        }
        // Load g tile + 256 halo into padded smem (zero-padded past T)
        for (int i = tid; i < TILE_J + LPAD; i += THREADS) {
            int gi = base + i;
            float v = (gi < T) ? g[gi] : 0.f;
            g_s[i + (i >> 3)] = v;
            if (i < TILE_J) { sg += v; sg2 += v * v; }
        }
        __syncthreads();

        // Sliding-window cross-correlation: acc[k] += sum_j p[j] * g[j + n0 + k]
        float w[8];
#pragma unroll
        for (int k = 0; k < 8; k++) {
            int li = jj0 + n0 + k;
            w[k] = g_s[li + (li >> 3)];
        }
#pragma unroll 8
        for (int jj = 0; jj < 128; jj++) {
            float pv = p_s[jj0 + jj];
#pragma unroll
            for (int k = 0; k < 8; k++) acc[k] = fmaf(pv, w[k], acc[k]);
            int li = jj0 + jj + n0 + 8;        // next window top (lane-stride 9 in phys -> no conflict)
            float nv = g_s[li + (li >> 3)];
#pragma unroll
            for (int k = 0; k < 7; k++) w[k] = w[k + 1];
            w[7] = nv;
        }
        __syncthreads();
    }

    // Reduce 8 warps' partials per lag -> one partial row per block
#pragma unroll
    for (int k = 0; k < 8; k++) red[warpId * LPAD + n0 + k] = acc[k];
    __syncthreads();
    {
        float s = 0.f;
#pragma unroll
        for (int w = 0; w < 8; w++) s += red[w * LPAD + tid];
        g_partial[blockIdx.x * LPAD + tid] = s;
    }

    // Reduce the 4 scalar sums
#pragma unroll
    for (int off = 16; off; off >>= 1) {
        sp  += __shfl_down_sync(0xFFFFFFFFu, sp,  off);
        sp2 += __shfl_down_sync(0xFFFFFFFFu, sp2, off);
        sg  += __shfl_down_sync(0xFFFFFFFFu, sg,  off);
        sg2 += __shfl_down_sync(0xFFFFFFFFu, sg2, off);
    }
    __shared__ float sred[8][4];
    if (lane == 0) {
        sred[warpId][0] = sp;  sred[warpId][1] = sp2;
        sred[warpId][2] = sg;  sred[warpId][3] = sg2;
    }
    __syncthreads();
    if (tid < 4) {
        float t = 0.f;
#pragma unroll
        for (int w = 0; w < 8; w++) t += sred[w][tid];
        ((float*)&g_sums4[blockIdx.x])[tid] = t;
    }
}

// ---------------------------------------------------------------------------
// Kernel B: deterministic finalize, now parallel + MLP-friendly.
//   1024 threads: lag = tid&255, chunk = tid>>8 handles 148 of the 592 rows
//   with 4 independent accumulators (16 loads in flight per lag).
//   g_sums reduced by float4 tree; tail prefix via Hillis-Steele scan.
// ---------------------------------------------------------------------------
#define FIN_THREADS 1024

__global__ void __launch_bounds__(FIN_THREADS) finalize_kernel(const float* __restrict__ p,
                                                               int T,
                                                               float* __restrict__ out) {
    __shared__ float  cr[4][LPAD];       // per-chunk cross partials
    __shared__ float4 r4[FIN_THREADS];   // g_sums tree reduction
    __shared__ float  scanA[LPAD], scanB[LPAD];   // ptail scan ping-pong
    __shared__ float  scan2A[LPAD], scan2B[LPAD]; // ptail^2 scan ping-pong
    __shared__ float  cccs[LPAD];
    __shared__ float4 tot;

    const int tid   = threadIdx.x;
    const int lag   = tid & (LPAD - 1);
    const int chunk = tid >> 8;          // 0..3

    // --- Stage 1: cross[lag] = sum over 592 blocks, chunked 4-way, unrolled 4x ---
    {
        float a0 = 0.f, a1 = 0.f, a2 = 0.f, a3 = 0.f;
        const int b0 = chunk * (NBLOCKS / 4);               // 148 rows per chunk
        const float* base = g_partial + b0 * LPAD + lag;
#pragma unroll 1
        for (int i = 0; i < NBLOCKS / 4; i += 4) {          // 37 rounds
            a0 += base[(i + 0) * LPAD];
            a1 += base[(i + 1) * LPAD];
            a2 += base[(i + 2) * LPAD];
            a3 += base[(i + 3) * LPAD];
        }
        cr[chunk][lag] = (a0 + a1) + (a2 + a3);
    }

    // --- Stage 2: g_sums float4 tree reduction ---
    {
        float4 v = make_float4(0.f, 0.f, 0.f, 0.f);
        if (tid < NBLOCKS) v = g_sums4[tid];
        r4[tid] = v;
    }
    __syncthreads();
#pragma unroll
    for (int off = FIN_THREADS / 2; off >= 1; off >>= 1) {
        if (tid < off) {
            float4 a = r4[tid], b = r4[tid + off];
            r4[tid] = make_float4(a.x + b.x, a.y + b.y, a.z + b.z, a.w + b.w);
        }
        __syncthreads();
    }
    if (tid == 0) tot = r4[0];

    // --- Stage 3: tail values + Hillis-Steele inclusive scan (8 steps) ---
    if (tid < LPAD) {
        float v = (tid >= 1) ? p[T - tid] : 0.f;
        scanA[tid]  = v;
        scan2A[tid] = v * v;
    }
    __syncthreads();
#pragma unroll
    for (int s = 0; s < 8; s++) {
        int off = 1 << s;
        if (tid < LPAD) {
            float a  = scanA[tid]  + ((tid >= off) ? scanA[tid - off]  : 0.f);
            float a2 = scan2A[tid] + ((tid >= off) ? scan2A[tid - off] : 0.f);
            scanB[tid] = a; scan2B[tid] = a2;
        }
        __syncthreads();
        if (tid < LPAD) { scanA[tid] = scanB[tid]; scan2A[tid] = scan2B[tid]; }
        __syncthreads();
    }

    // --- Stage 4: per-lag CCC + reduction ---
    if (tid < LPAD) {
        const float Sp  = tot.x, Sp2 = tot.y;
        const float Sg  = tot.z, Sg2 = tot.w;
        const float Tf  = (float)T;
        const float mean_gt = Sg / Tf;
        const float var_gt  = (Sg2 - Tf * mean_gt * mean_gt) / (Tf - 1.f);

        float ccc = 0.f;
        if (tid < NLAGS) {
            float cross = cr[0][tid] + cr[1][tid] + cr[2][tid] + cr[3][tid];
            float Spn   = Sp  - scanA[tid];     // sum of p[0 : T-n]
            float Spn2  = Sp2 - scan2A[tid];
            float mean_pred = Spn / Tf;
            float var_pred  = (Spn2 - Tf * mean_pred * mean_pred) / (Tf - 1.f);
            float cov = (cross - mean_gt * Spn) / Tf;   // population covariance
            float dm  = mean_gt - mean_pred;
            float denom = var_gt + var_pred + dm * dm;
            ccc = 2.f * cov / denom;
        }
        cccs[tid] = ccc;
    }
    __syncthreads();
#pragma unroll
    for (int off = LPAD / 2; off >= 1; off >>= 1) {
        if (tid < off) cccs[tid] += cccs[tid + off];
        __syncthreads();
    }
    if (tid == 0) out[0] = 1.f - cccs[0] / (float)NLAGS;
}

extern "C" void kernel_launch(void* const* d_in, const int* in_sizes, int n_in,
                              void* d_out, int out_size) {
    const float* pred = (const float*)d_in[0];
    const float* gt   = (const float*)d_in[1];
    float* out = (float*)d_out;
    int T = in_sizes[0];

    cccorr_kernel<<<NBLOCKS, THREADS>>>(pred, gt, T);
    finalize_kernel<<<1, FIN_THREADS>>>(pred, T, out);
}